// round 1
// baseline (speedup 1.0000x reference)
#include <cuda_runtime.h>

// Fixed problem shape: x [8, 256, 256, 256] fp32, r=2, out channels 64.
// out[n, 2h+r1, 2w+r2, c] = x[n, h, w, c*4 + r1*2 + r2]
//
// Each thread handles one input pixel's channel-group g (16 input channels =
// 64 bytes = 4 float4 loads, contiguous). The 4 float4s form a 4x4 matrix
// (rows: output channel c=4g+i, cols: output pixel off=(r1,r2)). Transpose in
// registers, emit 4 float4 stores (one per output pixel, channels 4g..4g+3).
// All loads and stores are 16B-vectorized and warp-coalesced.

static constexpr int B  = 8;
static constexpr int H  = 256;
static constexpr int W  = 256;
static constexpr int CO = 64;              // output channels
static constexpr int G  = CO / 4;          // 16 channel-groups per pixel
static constexpr long long NTHREADS = (long long)B * H * W * G;  // 8,388,608

__global__ __launch_bounds__(256)
void subpixel_upscale_kernel(const float4* __restrict__ in4,
                             float4* __restrict__ out4) {
    const unsigned idx = blockIdx.x * blockDim.x + threadIdx.x;

    // idx = (((n*H + h)*W + w)*G + g)
    const unsigned g = idx & (G - 1);
    const unsigned w = (idx >> 4) & (W - 1);
    const unsigned h = (idx >> 12) & (H - 1);
    const unsigned n = idx >> 20;

    // Input is linear in idx: base float4 index = idx*4 (64B per thread).
    const float4 a0 = in4[idx * 4 + 0];   // c = 4g+0, comps = off 0..3
    const float4 a1 = in4[idx * 4 + 1];   // c = 4g+1
    const float4 a2 = in4[idx * 4 + 2];   // c = 4g+2
    const float4 a3 = in4[idx * 4 + 3];   // c = 4g+3

    // Output float4 index for pixel (2h, 2w), channels 4g..4g+3:
    // ((n*(2H) + 2h)*(2W) + 2w)*G + g
    const unsigned OB = ((n * (2 * H) + 2 * h) * (2 * W) + 2 * w) * G + g;
    const unsigned ROW = (2 * W) * G;     // one output row in float4 units = 8192

    out4[OB]            = make_float4(a0.x, a1.x, a2.x, a3.x);  // (r1=0,r2=0)
    out4[OB + G]        = make_float4(a0.y, a1.y, a2.y, a3.y);  // (0,1)
    out4[OB + ROW]      = make_float4(a0.z, a1.z, a2.z, a3.z);  // (1,0)
    out4[OB + ROW + G]  = make_float4(a0.w, a1.w, a2.w, a3.w);  // (1,1)
}

extern "C" void kernel_launch(void* const* d_in, const int* in_sizes, int n_in,
                              void* d_out, int out_size) {
    const float4* in4 = (const float4*)d_in[0];
    float4* out4 = (float4*)d_out;

    const int threads = 256;
    const int blocks = (int)(NTHREADS / threads);   // 32768
    subpixel_upscale_kernel<<<blocks, threads>>>(in4, out4);
}